// round 2
// baseline (speedup 1.0000x reference)
#include <cuda_runtime.h>
#include <math.h>

#define NPTS    200000
#define NBINS   512
#define NGRP    16          // 16 groups x 32 bins; group g covers r in (0.16g, 0.16g+0.16]
#define SLICES  60          // accum blocks per group
#define WPB     8           // warps per accum block

// Per-group point lists (built each launch), counters, and partials.
__device__ int    g_cnt[NGRP];
__device__ float4 g_l1[NGRP * NPTS];   // (k, mneg, B, A2)
__device__ float  g_li[NGRP * NPTS];   // intensity
__device__ float  g_partial[NBINS * SLICES];

__device__ __forceinline__ float ex2f(float x) {
    float y;
    asm("ex2.approx.f32 %0, %1;" : "=f"(y) : "f"(x));
    return y;
}

// ---------------------------------------------------------------------------
__global__ void init_kernel() {
    if (threadIdx.x < NGRP) g_cnt[threadIdx.x] = 0;
}

// ---------------------------------------------------------------------------
// Kernel 1: per-point fold + bucket into per-group lists (warp-aggregated atomics)
// ---------------------------------------------------------------------------
__global__ void precompute_kernel(const float* __restrict__ means,
                                  const float* __restrict__ scan_point,
                                  const float* __restrict__ colours,
                                  const float* __restrict__ coefficients,
                                  const float* __restrict__ opacities,
                                  const float* __restrict__ scales)
{
    const int i    = blockIdx.x * blockDim.x + threadIdx.x;
    const int lane = threadIdx.x & 31;

    float4 p1 = make_float4(0.f, 0.f, 0.f, 0.f);
    float  I  = 0.f;
    int    g0 = 0, g1 = -1;               // empty range by default

    if (i < NPTS) {
        float sx = scan_point[0], sy = scan_point[1], sz = scan_point[2];
        float dx = means[3 * i + 0] - sx;
        float dy = means[3 * i + 1] - sy;
        float dz = means[3 * i + 2] - sz;
        float r0 = sqrtf(dx * dx + dy * dy + dz * dz);

        float sigma = fmaxf(expf(scales[i]), 0.005f);   // BIN_RES/2
        float sinv  = 1.0f / sigma;

        float coeff = 1.0f / (1.0f + expf(-coefficients[i]));

        float op = opacities[i];
        float co = colours[i];
        I = (op * op) * (co * co);

        // pdf*(h/2) = e * (A + B*(r - r0)),  folded: gg = fma(r, B, A2)
        float A  = 0.005f * coeff * 0.3989422804014327f * sinv;
        float B  = 0.005f * (1.0f - coeff) * sinv * sinv;
        float A2 = A - B * r0;

        // e = 2^(-(d*k)^2), k = sinv * sqrt(0.5*log2(e))
        float k    = 0.84932180028802f * sinv;
        float mneg = -r0 * k;
        p1 = make_float4(k, mneg, B, A2);

        // support window: u^2 <= 30  (tail e < 1e-9: invisible at 1e-3 rel err)
        float W   = 5.4772258f / k;
        float wlo = r0 - W;
        float whi = r0 + W;

        if (whi >= 0.005f && wlo <= 2.56f) {
            g0 = max(0,        (int)floorf((wlo - 0.005f) * 6.25f));
            g1 = min(NGRP - 1, (int)floorf((whi - 0.005f) * 6.25f));
        }
    }

    const unsigned lt = (1u << lane) - 1u;
    #pragma unroll
    for (int g = 0; g < NGRP; ++g) {
        bool want = (g >= g0) && (g <= g1);
        unsigned m = __ballot_sync(0xFFFFFFFFu, want);
        if (m == 0u) continue;
        int leader = __ffs(m) - 1;
        int base = 0;
        if (lane == leader) base = atomicAdd(&g_cnt[g], __popc(m));
        base = __shfl_sync(0xFFFFFFFFu, base, leader);
        if (want) {
            int slot = base + __popc(m & lt);
            g_l1[g * NPTS + slot] = p1;
            g_li[g * NPTS + slot] = I;
        }
    }
}

// ---------------------------------------------------------------------------
// Kernel 2: accumulate. Each warp = one group's 32 bins; streams a contiguous
// slice of that group's point list. 100% active, no branches in the hot loop.
// ---------------------------------------------------------------------------
__global__ void __launch_bounds__(256, 8) accum_kernel()
{
    __shared__ float4 s1[WPB][32];
    __shared__ float  si[WPB][32];
    __shared__ float  red[WPB][32];

    const int   g    = blockIdx.x;
    const int   w    = threadIdx.x >> 5;
    const int   lane = threadIdx.x & 31;
    const float rt   = 0.005f * (float)(g * 32 + lane + 1);

    const int n     = g_cnt[g];
    const int wid   = blockIdx.y * WPB + w;
    const int nw    = SLICES * WPB;
    const int chunk = (n + nw - 1) / nw;
    const int start = wid * chunk;
    const int end   = min(n, start + chunk);

    const float4* __restrict__ l1 = g_l1 + (size_t)g * NPTS;
    const float*  __restrict__ li = g_li + (size_t)g * NPTS;

    float acc = 0.0f;
    for (int t = start; t < end; t += 32) {
        const int cnt = min(32, end - t);
        if (lane < cnt) {
            s1[w][lane] = l1[t + lane];
            si[w][lane] = li[t + lane];
        }
        __syncwarp();
        #pragma unroll 4
        for (int j = 0; j < cnt; ++j) {
            float4 p  = s1[w][j];
            float  u  = fmaf(rt, p.x, p.y);     // (r - r0) * k
            float  e  = ex2f(-u * u);           // exp(-0.5 (d/sigma)^2)
            float  gg = fmaf(rt, p.z, p.w);     // A + B*(r - r0)
            float  pr = __saturatef(e * gg);    // clip(pdf*h/2, 0, 1)
            acc = fmaf(si[w][j], pr, acc);      // += I * pr
        }
        __syncwarp();
    }

    red[w][lane] = acc;
    __syncthreads();
    if (threadIdx.x < 32) {
        float s = 0.0f;
        #pragma unroll
        for (int ww = 0; ww < WPB; ++ww) s += red[ww][threadIdx.x];
        g_partial[(g * 32 + threadIdx.x) * SLICES + blockIdx.y] = s;
    }
}

// ---------------------------------------------------------------------------
// Kernel 3: deterministic reduce over SLICES partials + 1/r^2 scaling
// ---------------------------------------------------------------------------
__global__ void reduce_kernel(float* __restrict__ out)
{
    const int b    = blockIdx.x;     // 512 blocks, 32 threads
    const int lane = threadIdx.x;

    float s = 0.0f;
    for (int j = lane; j < SLICES; j += 32)
        s += g_partial[b * SLICES + j];

    #pragma unroll
    for (int o = 16; o > 0; o >>= 1)
        s += __shfl_xor_sync(0xFFFFFFFFu, s, o);

    if (lane == 0) {
        float r = 0.005f * (float)(b + 1);
        out[b] = s / (r * r);
    }
}

// ---------------------------------------------------------------------------
extern "C" void kernel_launch(void* const* d_in, const int* in_sizes, int n_in,
                              void* d_out, int out_size)
{
    const float* means        = (const float*)d_in[0];
    const float* scan_point   = (const float*)d_in[1];
    const float* colours      = (const float*)d_in[2];
    const float* coefficients = (const float*)d_in[3];
    const float* opacities    = (const float*)d_in[4];
    const float* scales       = (const float*)d_in[5];

    float* out = (float*)d_out;

    init_kernel<<<1, 32>>>();
    precompute_kernel<<<(NPTS + 255) / 256, 256>>>(means, scan_point, colours,
                                                   coefficients, opacities, scales);
    accum_kernel<<<dim3(NGRP, SLICES), 256>>>();
    reduce_kernel<<<NBINS, 32>>>(out);
}

// round 3
// speedup vs baseline: 1.8430x; 1.8430x over previous
#include <cuda_runtime.h>
#include <math.h>

#define NPTS    200000
#define NBINS   512
#define BLOCKS  296       // 2 blocks/SM on 148 SMs, single wave
#define TPB     256
#define WPB     8         // warps per block

// Per-block partial histograms (block-major for coalesced reduce).
__device__ float g_partial[BLOCKS * NBINS];

__device__ __forceinline__ float ex2f(float x) {
    float y;
    asm("ex2.approx.f32 %0, %1;" : "=f"(y) : "f"(x));
    return y;
}

// ---------------------------------------------------------------------------
// Kernel 1 (fused): fold per-point params + cooperative warp-wide scatter into
// per-warp private shared histograms. No atomics, no wasted bin visits.
// ---------------------------------------------------------------------------
__global__ void __launch_bounds__(TPB, 2) main_kernel(
        const float* __restrict__ means,
        const float* __restrict__ scan_point,
        const float* __restrict__ colours,
        const float* __restrict__ coefficients,
        const float* __restrict__ opacities,
        const float* __restrict__ scales)
{
    __shared__ float  hist[WPB][NBINS];   // 16 KB: per-warp private hist
    __shared__ float4 sp[WPB][32];        //  4 KB: staged (k, mneg, B, A2)
    __shared__ float2 sq[WPB][32];        //  2 KB: staged (I, packed b0|nb)

    const int w    = threadIdx.x >> 5;
    const int lane = threadIdx.x & 31;

    // zero own warp's hist
    #pragma unroll
    for (int t = 0; t < NBINS / 32; ++t) hist[w][lane + 32 * t] = 0.0f;
    __syncwarp();

    const int chunk  = (NPTS + BLOCKS - 1) / BLOCKS;   // 676
    const int bstart = blockIdx.x * chunk;
    const int bend   = min(NPTS, bstart + chunk);
    const int wchunk = (chunk + WPB - 1) / WPB;        // 85
    const int wstart = bstart + w * wchunk;
    const int wend   = min(bend, wstart + wchunk);

    const float sx = scan_point[0], sy = scan_point[1], sz = scan_point[2];

    for (int t = wstart; t < wend; t += 32) {
        // ---- fold phase: lane -> one point ----
        int p = t + lane;
        float4 P  = make_float4(0.f, 0.f, 0.f, 0.f);
        float  I  = 0.f;
        int    pk = 0;
        if (p < wend) {
            float dx = means[3 * p + 0] - sx;
            float dy = means[3 * p + 1] - sy;
            float dz = means[3 * p + 2] - sz;
            float r0 = sqrtf(fmaf(dx, dx, fmaf(dy, dy, dz * dz)));

            float sigma = fmaxf(__expf(scales[p]), 0.005f);   // BIN_RES/2
            float sinv  = __frcp_rn(sigma);

            float coeff = __frcp_rn(1.0f + __expf(-coefficients[p]));

            float op = opacities[p];
            float co = colours[p];
            I = (op * op) * (co * co);

            // pdf*(h/2) = e * (A + B*(r-r0));  gg = fma(r, B, A2)
            float A  = 0.005f * 0.3989422804014327f * coeff * sinv;
            float B  = 0.005f * (1.0f - coeff) * sinv * sinv;
            float A2 = A - B * r0;

            // e = 2^(-(d*k)^2), k = sinv*sqrt(0.5*log2 e)
            float k    = 0.84932180028802f * sinv;
            float mneg = -r0 * k;
            P = make_float4(k, mneg, B, A2);

            // support window: |u| <= 5.2*sigma*k equivalent (4.4165 = 5.2*0.84932)
            float W   = 4.41647f / k;
            // bin i (0-based) has r = 0.005*(i+1); keep bins with r in [r0-W, r0+W]
            int b0 = max(0,   (int)ceilf ((r0 - W) * 200.0f - 1.0f));
            int b1 = min(511, (int)floorf((r0 + W) * 200.0f - 1.0f));
            int nb = max(0, b1 - b0 + 1);
            pk = b0 | (nb << 16);
        }
        sp[w][lane] = P;
        sq[w][lane] = make_float2(I, __int_as_float(pk));
        __syncwarp();

        // ---- scatter phase: warp sweeps each point's bin window ----
        const int cnt = min(32, wend - t);
        for (int j = 0; j < cnt; ++j) {
            float2 iq = sq[w][j];
            int pkj = __float_as_int(iq.y);
            int nb  = pkj >> 16;
            if (nb == 0) continue;                // warp-uniform
            float4 q  = sp[w][j];
            int   b0  = pkj & 0xFFFF;
            float Ij  = iq.x;
            float rt  = 0.005f * (float)(b0 + lane + 1);
            const int iters = (nb + 31) >> 5;
            for (int s = 0; s < iters; ++s) {
                int idx = (s << 5) + lane;
                float u  = fmaf(rt, q.x, q.y);    // (r - r0) * k
                float e  = ex2f(-u * u);          // exp(-0.5 (d/sig)^2)
                float gg = fmaf(rt, q.z, q.w);    // A + B*(r - r0)
                float pr = __saturatef(e * gg);   // clip(pdf*h/2, 0, 1)
                if (idx < nb) {
                    int b = b0 + idx;
                    hist[w][b] = fmaf(Ij, pr, hist[w][b]);
                }
                rt += 0.16f;                      // 32 * 0.005
            }
        }
        __syncwarp();
    }

    // ---- merge 8 warp hists -> block partial (deterministic) ----
    __syncthreads();
    for (int b = threadIdx.x; b < NBINS; b += TPB) {
        float s = 0.0f;
        #pragma unroll
        for (int ww = 0; ww < WPB; ++ww) s += hist[ww][b];
        g_partial[blockIdx.x * NBINS + b] = s;
    }
}

// ---------------------------------------------------------------------------
// Kernel 2: reduce BLOCKS partials per bin + 1/r^2 scaling (deterministic)
// ---------------------------------------------------------------------------
__global__ void reduce_kernel(float* __restrict__ out)
{
    const int b = blockIdx.x * 32 + threadIdx.x;   // grid 16 x 32 = 512 bins
    float s = 0.0f;
    #pragma unroll 8
    for (int j = 0; j < BLOCKS; ++j)
        s += g_partial[j * NBINS + b];
    float r = 0.005f * (float)(b + 1);
    out[b] = s / (r * r);
}

// ---------------------------------------------------------------------------
extern "C" void kernel_launch(void* const* d_in, const int* in_sizes, int n_in,
                              void* d_out, int out_size)
{
    const float* means        = (const float*)d_in[0];
    const float* scan_point   = (const float*)d_in[1];
    const float* colours      = (const float*)d_in[2];
    const float* coefficients = (const float*)d_in[3];
    const float* opacities    = (const float*)d_in[4];
    const float* scales       = (const float*)d_in[5];

    float* out = (float*)d_out;

    main_kernel<<<BLOCKS, TPB>>>(means, scan_point, colours,
                                 coefficients, opacities, scales);
    reduce_kernel<<<16, 32>>>(out);
}

// round 4
// speedup vs baseline: 2.8409x; 1.5415x over previous
#include <cuda_runtime.h>
#include <math.h>

#define NPTS    200000
#define NBINS   512
#define BLOCKS  296       // 2 blocks/SM on 148 SMs, single wave
#define TPB     256
#define WPB     8         // warps per block

// Per-block partial histograms, BIN-MAJOR: g_partial[bin*BLOCKS + block].
// Scattered writes from main (hidden by occupancy), coalesced reads in reduce.
__device__ float g_partial[NBINS * BLOCKS];

__device__ __forceinline__ float ex2f(float x) {
    float y;
    asm("ex2.approx.f32 %0, %1;" : "=f"(y) : "f"(x));
    return y;
}

// ---------------------------------------------------------------------------
// Kernel 1 (fused): fold per-point params + cooperative warp-wide scatter into
// per-warp private shared histograms. No atomics, no wasted bin visits.
// ---------------------------------------------------------------------------
__global__ void __launch_bounds__(TPB, 2) main_kernel(
        const float* __restrict__ means,
        const float* __restrict__ scan_point,
        const float* __restrict__ colours,
        const float* __restrict__ coefficients,
        const float* __restrict__ opacities,
        const float* __restrict__ scales)
{
    __shared__ float  hist[WPB][NBINS];   // 16 KB: per-warp private hist
    __shared__ float4 sp[WPB][32];        //  4 KB: staged (k, mneg, B, A2)
    __shared__ float2 sq[WPB][32];        //  2 KB: staged (I, packed b0|nb)

    const int w    = threadIdx.x >> 5;
    const int lane = threadIdx.x & 31;

    // zero own warp's hist
    #pragma unroll
    for (int t = 0; t < NBINS / 32; ++t) hist[w][lane + 32 * t] = 0.0f;
    __syncwarp();

    const int chunk  = (NPTS + BLOCKS - 1) / BLOCKS;   // 676
    const int bstart = blockIdx.x * chunk;
    const int bend   = min(NPTS, bstart + chunk);
    const int wchunk = (chunk + WPB - 1) / WPB;        // 85
    const int wstart = bstart + w * wchunk;
    const int wend   = min(bend, wstart + wchunk);

    const float sx = scan_point[0], sy = scan_point[1], sz = scan_point[2];

    for (int t = wstart; t < wend; t += 32) {
        // ---- fold phase: lane -> one point ----
        int p = t + lane;
        float4 P  = make_float4(0.f, 0.f, 0.f, 0.f);
        float  I  = 0.f;
        int    pk = 0;
        if (p < wend) {
            float dx = means[3 * p + 0] - sx;
            float dy = means[3 * p + 1] - sy;
            float dz = means[3 * p + 2] - sz;
            float r0 = sqrtf(fmaf(dx, dx, fmaf(dy, dy, dz * dz)));

            float sigma = fmaxf(__expf(scales[p]), 0.005f);   // BIN_RES/2
            float sinv  = __frcp_rn(sigma);

            float coeff = __frcp_rn(1.0f + __expf(-coefficients[p]));

            float op = opacities[p];
            float co = colours[p];
            I = (op * op) * (co * co);

            // pdf*(h/2) = e * (A + B*(r-r0));  gg = fma(r, B, A2)
            float A  = 0.005f * 0.3989422804014327f * coeff * sinv;
            float B  = 0.005f * (1.0f - coeff) * sinv * sinv;
            float A2 = A - B * r0;

            // e = 2^(-(d*k)^2), k = sinv*sqrt(0.5*log2 e)
            float k    = 0.84932180028802f * sinv;
            float mneg = -r0 * k;
            P = make_float4(k, mneg, B, A2);

            // support window: 4.41647/k ~ 5.2 sigma (tail < 1.4e-6, invisible)
            float W   = 4.41647f / k;
            // bin i (0-based) has r = 0.005*(i+1); keep bins with r in [r0-W, r0+W]
            int b0 = max(0,   (int)ceilf ((r0 - W) * 200.0f - 1.0f));
            int b1 = min(511, (int)floorf((r0 + W) * 200.0f - 1.0f));
            int nb = max(0, b1 - b0 + 1);
            pk = b0 | (nb << 16);
        }
        sp[w][lane] = P;
        sq[w][lane] = make_float2(I, __int_as_float(pk));
        __syncwarp();

        // ---- scatter phase: warp sweeps each point's bin window ----
        const int cnt = min(32, wend - t);
        for (int j = 0; j < cnt; ++j) {
            float2 iq = sq[w][j];
            int pkj = __float_as_int(iq.y);
            int nb  = pkj >> 16;
            if (nb == 0) continue;                // warp-uniform
            float4 q  = sp[w][j];
            int   b0  = pkj & 0xFFFF;
            float Ij  = iq.x;
            float rt  = 0.005f * (float)(b0 + lane + 1);
            const int iters = (nb + 31) >> 5;
            for (int s = 0; s < iters; ++s) {
                int idx = (s << 5) + lane;
                float u  = fmaf(rt, q.x, q.y);    // (r - r0) * k
                float e  = ex2f(-u * u);          // exp(-0.5 (d/sig)^2)
                float gg = fmaf(rt, q.z, q.w);    // A + B*(r - r0)
                float pr = __saturatef(e * gg);   // clip(pdf*h/2, 0, 1)
                if (idx < nb) {
                    int b = b0 + idx;
                    hist[w][b] = fmaf(Ij, pr, hist[w][b]);
                }
                rt += 0.16f;                      // 32 * 0.005
            }
        }
        __syncwarp();
    }

    // ---- merge 8 warp hists -> block partial (bin-major, deterministic) ----
    __syncthreads();
    for (int b = threadIdx.x; b < NBINS; b += TPB) {
        float s = 0.0f;
        #pragma unroll
        for (int ww = 0; ww < WPB; ++ww) s += hist[ww][b];
        g_partial[b * BLOCKS + blockIdx.x] = s;
    }
}

// ---------------------------------------------------------------------------
// Kernel 2: reduce. One block per bin; 128 threads sum 296 contiguous
// partials (coalesced, L2-resident), shfl+shared tree. Deterministic.
// ---------------------------------------------------------------------------
__global__ void __launch_bounds__(128) reduce_kernel(float* __restrict__ out)
{
    __shared__ float red[4];
    const int b    = blockIdx.x;
    const int tid  = threadIdx.x;
    const int lane = tid & 31;
    const int w    = tid >> 5;

    const float* __restrict__ row = g_partial + b * BLOCKS;

    float s = 0.0f;
    #pragma unroll
    for (int j = tid; j < BLOCKS; j += 128)   // <= 3 iterations
        s += row[j];

    #pragma unroll
    for (int o = 16; o > 0; o >>= 1)
        s += __shfl_xor_sync(0xFFFFFFFFu, s, o);

    if (lane == 0) red[w] = s;
    __syncthreads();
    if (tid == 0) {
        float tot = red[0] + red[1] + red[2] + red[3];
        float r = 0.005f * (float)(b + 1);
        out[b] = tot / (r * r);
    }
}

// ---------------------------------------------------------------------------
extern "C" void kernel_launch(void* const* d_in, const int* in_sizes, int n_in,
                              void* d_out, int out_size)
{
    const float* means        = (const float*)d_in[0];
    const float* scan_point   = (const float*)d_in[1];
    const float* colours      = (const float*)d_in[2];
    const float* coefficients = (const float*)d_in[3];
    const float* opacities    = (const float*)d_in[4];
    const float* scales       = (const float*)d_in[5];

    float* out = (float*)d_out;

    main_kernel<<<BLOCKS, TPB>>>(means, scan_point, colours,
                                 coefficients, opacities, scales);
    reduce_kernel<<<NBINS, 128>>>(out);
}